// round 8
// baseline (speedup 1.0000x reference)
#include <cuda_runtime.h>
#include <math.h>
#include <stdint.h>

#define MAXB 8192

__device__ float g_conv1[(size_t)MAXB * 64 * 400];   // [B,64,20,20]
__device__ float g_pool1[(size_t)MAXB * 64 * 100];   // [B,64,10,10]
__device__ float g_conv2[(size_t)MAXB * 128 * 100];  // [B,128,10,10]
__device__ float g_pool2[(size_t)MAXB * 128 * 25];   // [B,128,5,5]
__device__ float g_conv3[(size_t)MAXB * 256 * 25];   // [B,256,5,5]
__device__ float g_feat [(size_t)25 * MAXB * 256];   // [25,B,256]
__device__ float g_preds[(size_t)25 * MAXB * 10];    // [25,B,10]
__device__ float g_scale[704];
__device__ float g_bias[704];
// pre-transposed, tf32-split conv weights: Wt[k][oc], k = ic*9 + ky*3 + kx
__device__ float g_wt2h[576 * 128],  g_wt2l[576 * 128];
__device__ float g_wt3h[1152 * 256], g_wt3l[1152 * 256];
__device__ float g_wt4h[2304 * 256], g_wt4l[2304 * 256];

typedef unsigned int uint32;
typedef unsigned long long ull;

// ---------------------------------------------------------------------------
// tf32 helpers: split fp32 into hi+lo tf32 (3-MMA emulation ~ fp32 precision)
// ---------------------------------------------------------------------------
__device__ __forceinline__ uint32 f2tf(float x) {
    uint32 r;
    asm("cvt.rna.tf32.f32 %0, %1;" : "=r"(r) : "f"(x));
    return r;
}
__device__ __forceinline__ void split_tf(float x, uint32& h, uint32& l) {
    h = f2tf(x);
    l = f2tf(x - __uint_as_float(h));
}
__device__ __forceinline__ void mma_tf32(float* c, uint32 a0, uint32 a1, uint32 a2, uint32 a3,
                                         uint32 b0, uint32 b1) {
    asm volatile(
        "mma.sync.aligned.m16n8k8.row.col.f32.tf32.tf32.f32 "
        "{%0,%1,%2,%3},{%4,%5,%6,%7},{%8,%9},{%0,%1,%2,%3};"
        : "+f"(c[0]), "+f"(c[1]), "+f"(c[2]), "+f"(c[3])
        : "r"(a0), "r"(a1), "r"(a2), "r"(a3), "r"(b0), "r"(b1));
}

// FFMA2 helpers (used by conv1 only)
__device__ __forceinline__ ull pack2(float lo, float hi) {
    ull r; asm("mov.b64 %0, {%1, %2};" : "=l"(r) : "f"(lo), "f"(hi)); return r;
}
__device__ __forceinline__ void fma2(ull& d, ull a, ull b) {
    asm("fma.rn.f32x2 %0, %1, %2, %3;" : "=l"(d) : "l"(a), "l"(b), "l"(d));
}
__device__ __forceinline__ void unpack2(ull v, float& lo, float& hi) {
    asm("mov.b64 {%0, %1}, %2;" : "=f"(lo), "=f"(hi) : "l"(v));
}

// ---------------------------------------------------------------------------
// BN fold
// ---------------------------------------------------------------------------
__global__ void bn_prep(const float* __restrict__ b, const float* __restrict__ g,
                        const float* __restrict__ be, const float* __restrict__ m,
                        const float* __restrict__ v, int C, int off)
{
    int c = blockIdx.x * blockDim.x + threadIdx.x;
    if (c < C) {
        float sc = g[c] / sqrtf(v[c] + 1e-5f);
        g_scale[off + c] = sc;
        g_bias[off + c]  = (b[c] - m[c]) * sc + be[c];
    }
}

// ---------------------------------------------------------------------------
// Weight prep: transpose [oc][k] -> [k][oc] and split to tf32 hi/lo
// ---------------------------------------------------------------------------
__global__ void wprep(const float* __restrict__ w, float* __restrict__ wh,
                      float* __restrict__ wl, int OCT, int K)
{
    int idx = blockIdx.x * blockDim.x + threadIdx.x;
    if (idx >= OCT * K) return;
    int oc = idx / K, k = idx - oc * K;
    uint32 h, l;
    split_tf(w[idx], h, l);
    wh[(size_t)k * OCT + oc] = __uint_as_float(h);
    wl[(size_t)k * OCT + oc] = __uint_as_float(l);
}

// ---------------------------------------------------------------------------
// conv1 only: scalar FFMA2 kernel (3 input channels — not worth tensor cores)
// ---------------------------------------------------------------------------
template<int IC, int OC, int ICCHUNK, int HW, int NTHREADS>
__launch_bounds__(NTHREADS, 2)
__global__ void conv_bn_relu_kernel(const float* __restrict__ in,
                                    const float* __restrict__ wt,
                                    const float* __restrict__ ks,
                                    const float* __restrict__ kb,
                                    float* __restrict__ out, int B)
{
    constexpr int TILES = HW / 5;
    constexpr int CH9 = ICCHUNK * 9;
    constexpr int WSTRIDE = (CH9 % 2 == 0) ? (CH9 + 1) : CH9;

    extern __shared__ float dyn[];
    float* in_s = dyn;
    float* w_s  = dyn + ICCHUNK * 49;

    const int tile = blockIdx.x;
    const int b    = blockIdx.y;
    const int ty0  = (tile / TILES) * 5;
    const int tx0  = (tile % TILES) * 5;
    const int oc   = threadIdx.x;

    ull   accp[5][2];
    float acc4[5];
    #pragma unroll
    for (int r = 0; r < 5; r++) { accp[r][0] = 0ull; accp[r][1] = 0ull; acc4[r] = 0.f; }

    for (int ic0 = 0; ic0 < IC; ic0 += ICCHUNK) {
        __syncthreads();
        for (int idx = threadIdx.x; idx < ICCHUNK * 49; idx += NTHREADS) {
            int i = idx / 49, r = idx % 49;
            int y = ty0 - 1 + r / 7;
            int x = tx0 - 1 + r % 7;
            float v = 0.f;
            if (y >= 0 && y < HW && x >= 0 && x < HW)
                v = in[(((size_t)b * IC + ic0 + i) * HW + y) * HW + x];
            in_s[idx] = v;
        }
        for (int idx = threadIdx.x; idx < OC * CH9; idx += NTHREADS) {
            int o = idx / CH9, r = idx % CH9;
            w_s[o * WSTRIDE + r] = wt[((size_t)o * IC + ic0) * 9 + r];
        }
        __syncthreads();

        #pragma unroll 1
        for (int i = 0; i < ICCHUNK; i++) {
            float ws[9]; ull wp2[9];
            const float* wq = &w_s[oc * WSTRIDE + i * 9];
            #pragma unroll
            for (int k = 0; k < 9; k++) { ws[k] = wq[k]; wp2[k] = pack2(ws[k], ws[k]); }
            #pragma unroll
            for (int r = 0; r < 7; r++) {
                float iv[7];
                #pragma unroll
                for (int c = 0; c < 7; c++) iv[c] = in_s[i * 49 + r * 7 + c];
                ull pr[5];
                #pragma unroll
                for (int s = 0; s < 5; s++) pr[s] = pack2(iv[s], iv[s + 1]);
                #pragma unroll
                for (int ky = 0; ky < 3; ky++) {
                    const int py = r - ky;
                    if (py >= 0 && py < 5) {
                        #pragma unroll
                        for (int kx = 0; kx < 3; kx++) {
                            fma2(accp[py][0], wp2[ky * 3 + kx], pr[kx]);
                            fma2(accp[py][1], wp2[ky * 3 + kx], pr[kx + 2]);
                            acc4[py] = fmaf(ws[ky * 3 + kx], iv[kx + 4], acc4[py]);
                        }
                    }
                }
            }
        }
    }

    float s  = ks[oc];
    float bs = kb[oc];
    #pragma unroll
    for (int py = 0; py < 5; py++) {
        float v0, v1, v2, v3;
        unpack2(accp[py][0], v0, v1);
        unpack2(accp[py][1], v2, v3);
        float row[5] = { v0, v1, v2, v3, acc4[py] };
        #pragma unroll
        for (int px = 0; px < 5; px++) {
            float y = fmaxf(fmaf(row[px], s, bs), 0.f);
            out[(((size_t)b * OC + oc) * HW + ty0 + py) * HW + tx0 + px] = y;
        }
    }
}

// ---------------------------------------------------------------------------
// Implicit-GEMM conv via tensor cores (tf32 split, 3-MMA).
// Block: IMGS images x OCB out-channels. M rows = IMGS*PPI pixel slots.
// K = IC*9 in chunks of 48; smem im2col tile Ah/Al[M][52], weights Wh/Wl[48][OCB+8].
// 8 warps; MT=4: warp = (row tile w&3, col half w>>2); MT=8: warp = row tile w.
// ---------------------------------------------------------------------------
template<int IC, int OCT, int OCB, int HW, int IMGS, int M, bool FEATOUT>
__launch_bounds__(256)
__global__ void conv_mma_kernel(const float* __restrict__ in,
                                const float* __restrict__ wth,
                                const float* __restrict__ wtl,
                                const float* __restrict__ ks,
                                const float* __restrict__ kb,
                                float* __restrict__ out, int B)
{
    constexpr int K   = IC * 9;
    constexpr int KC  = 48;
    constexpr int HW2 = HW * HW;
    constexpr int PPI = M / IMGS;       // 32 (HW=5) or 128 (HW=10)
    constexpr int MT  = M / 16;
    constexpr int AS  = 52;             // A stride: 52 % 32 == 4*... (4g+tig distinct)
    constexpr int WS  = OCB + 8;        // B stride: ≡ 8 mod 32

    extern __shared__ uint32 sm[];
    uint32* Ah = sm;
    uint32* Al = Ah + M * AS;
    uint32* Wh = Al + M * AS;
    uint32* Wl = Wh + KC * WS;

    const int b0   = blockIdx.x * IMGS;
    const int ocb0 = blockIdx.y * OCB;
    const int tid  = threadIdx.x;
    const int w    = tid >> 5;
    const int lane = tid & 31;
    const int g    = lane >> 2;
    const int tig  = lane & 3;
    const int rt    = (MT == 4) ? (w & 3) : w;
    const int cbase = (MT == 4) ? ((w >> 2) * 64) : 0;

    float acc[8][4];
    #pragma unroll
    for (int j = 0; j < 8; j++)
        #pragma unroll
        for (int q = 0; q < 4; q++) acc[j][q] = 0.f;

    const uint32* wthu = (const uint32*)wth;
    const uint32* wtlu = (const uint32*)wtl;

    for (int kc = 0; kc < K; kc += KC) {
        __syncthreads();
        // im2col A tile build (hi/lo split)
        for (int idx = tid; idx < M * KC; idx += 256) {
            int row = idx / KC, kk = idx - row * KC;
            int k = kc + kk;
            int c = k / 9, t = k - c * 9;
            int ky = t / 3, kx = t - ky * 3;
            int img, p;
            if (IMGS == 2) { img = row >> 5; p = row & 31; }
            else           { img = 0;        p = row; }
            float v = 0.f;
            if (p < HW2) {
                int py = p / HW, px = p - py * HW;
                int iy = py + ky - 1, ix = px + kx - 1;
                if (iy >= 0 && iy < HW && ix >= 0 && ix < HW)
                    v = in[((size_t)(b0 + img) * IC + c) * HW2 + iy * HW + ix];
            }
            uint32 h, l;
            split_tf(v, h, l);
            Ah[row * AS + kk] = h;
            Al[row * AS + kk] = l;
        }
        // weight tile (pre-split in gmem, coalesced copy)
        for (int idx = tid; idx < KC * OCB; idx += 256) {
            int kk = idx / OCB, oc = idx - kk * OCB;
            size_t gidx = (size_t)(kc + kk) * OCT + ocb0 + oc;
            Wh[kk * WS + oc] = wthu[gidx];
            Wl[kk * WS + oc] = wtlu[gidx];
        }
        __syncthreads();

        #pragma unroll
        for (int ksi = 0; ksi < KC / 8; ksi++) {
            const int k0 = ksi * 8;
            const int ra = (16 * rt + g) * AS + k0 + tig;
            const int rb = (16 * rt + g + 8) * AS + k0 + tig;
            uint32 ah0 = Ah[ra],     ah1 = Ah[rb];
            uint32 ah2 = Ah[ra + 4], ah3 = Ah[rb + 4];
            uint32 al0 = Al[ra],     al1 = Al[rb];
            uint32 al2 = Al[ra + 4], al3 = Al[rb + 4];
            #pragma unroll
            for (int j = 0; j < 8; j++) {
                const int col = cbase + 8 * j + g;
                uint32 bh0 = Wh[(k0 + tig) * WS + col];
                uint32 bh1 = Wh[(k0 + tig + 4) * WS + col];
                uint32 bl0 = Wl[(k0 + tig) * WS + col];
                uint32 bl1 = Wl[(k0 + tig + 4) * WS + col];
                mma_tf32(acc[j], al0, al1, al2, al3, bh0, bh1);
                mma_tf32(acc[j], ah0, ah1, ah2, ah3, bl0, bl1);
                mma_tf32(acc[j], ah0, ah1, ah2, ah3, bh0, bh1);
            }
        }
    }

    // epilogue: BN + ReLU + store (C frag: rows 16rt+g/+8, cols cbase+8j+2tig/+1)
    const int r0 = 16 * rt + g;
    const int r1 = r0 + 8;
    #pragma unroll
    for (int j = 0; j < 8; j++) {
        int c0 = cbase + 8 * j + 2 * tig;
        int oc0 = ocb0 + c0;
        float s0 = ks[oc0],     bb0 = kb[oc0];
        float s1 = ks[oc0 + 1], bb1 = kb[oc0 + 1];
        float y00 = fmaxf(fmaf(acc[j][0], s0, bb0), 0.f);
        float y01 = fmaxf(fmaf(acc[j][1], s1, bb1), 0.f);
        float y10 = fmaxf(fmaf(acc[j][2], s0, bb0), 0.f);
        float y11 = fmaxf(fmaf(acc[j][3], s1, bb1), 0.f);
        #pragma unroll
        for (int half = 0; half < 2; half++) {
            int row = half ? r1 : r0;
            float ya = half ? y10 : y00;
            float yb = half ? y11 : y01;
            int img, p;
            if (IMGS == 2) { img = row >> 5; p = row & 31; }
            else           { img = 0;        p = row; }
            if (p < HW2) {
                if (FEATOUT) {
                    size_t base = ((size_t)p * B + b0 + img) * OCT + oc0;
                    out[base]     = ya;
                    out[base + 1] = yb;
                } else {
                    out[((size_t)(b0 + img) * OCT + oc0) * HW2 + p]       = ya;
                    out[((size_t)(b0 + img) * OCT + oc0 + 1) * HW2 + p]   = yb;
                }
            }
        }
    }
}

// ---------------------------------------------------------------------------
// MaxPool2d(3, s=2, p=1)
// ---------------------------------------------------------------------------
__global__ void maxpool_kernel(const float* __restrict__ in, float* __restrict__ out,
                               int B, int C, int H)
{
    int OH = H / 2;
    size_t total = (size_t)B * C * OH * OH;
    size_t idx = (size_t)blockIdx.x * blockDim.x + threadIdx.x;
    if (idx >= total) return;
    int ox = idx % OH;
    int oy = (idx / OH) % OH;
    size_t bc = idx / ((size_t)OH * OH);
    const float* p = in + bc * H * H;
    float m = -3.4e38f;
    #pragma unroll
    for (int dy = -1; dy <= 1; dy++) {
        int iy = 2 * oy + dy;
        if (iy < 0 || iy >= H) continue;
        #pragma unroll
        for (int dx = -1; dx <= 1; dx++) {
            int ix = 2 * ox + dx;
            if (ix < 0 || ix >= H) continue;
            m = fmaxf(m, p[iy * H + ix]);
        }
    }
    out[idx] = m;
}

// ---------------------------------------------------------------------------
// Neighbor table (exact reference ordering, w=h=5)
// ---------------------------------------------------------------------------
__device__ __forceinline__ int nei_of(int i, int j)
{
    int n[8]; int cnt = 0;
    if (i - 5 >= 0)                          n[cnt++] = i - 5;
    if (i % 5 != 0)                          n[cnt++] = i - 1;
    if ((i + 1) % 5 != 0)                    n[cnt++] = i + 1;
    if (i + 5 < 25)                          n[cnt++] = i + 5;
    if (i - 6 >= 0 && i % 5 != 0)            n[cnt++] = i - 6;
    if (i - 4 >= 0 && (i + 1) % 5 != 0)      n[cnt++] = i - 4;
    if (i + 4 < 25 && i % 5 != 0)            n[cnt++] = i + 4;
    if (i + 6 < 25 && (i + 1) % 5 != 0)      n[cnt++] = i + 6;
    while (cnt < 8) n[cnt++] = -1;
    return n[j];
}

// ---------------------------------------------------------------------------
// Fused per-node MLP: tensor-core X@Wa (tf32 split, 3-MMA), tanh,
// scalar logits GEMM (600x10), softmax. Block = 64 batch x node.
// ---------------------------------------------------------------------------
template<int KDIM, bool STAGE2>
__launch_bounds__(256)
__global__ void mlp_kernel(const float* __restrict__ feat,   // [25][B][256]
                           const float* __restrict__ preds,  // [25][B][10]
                           const float* __restrict__ Wa,     // [25][336][600]
                           const float* __restrict__ ba,     // [25][600]
                           const float* __restrict__ Wb,     // [25][600][10]
                           const float* __restrict__ bb,     // [25][10]
                           float* __restrict__ outp,         // [25][B][10]
                           int B)
{
    constexpr int XS = 36;   // X stride (4g+tig distinct mod 32)
    constexpr int WWS = 72;  // W stride (8tig+g distinct mod 32)
    extern __shared__ uint32 smu[];
    uint32* Xh = smu;                       // 64*36
    uint32* Xl = Xh + 64 * XS;
    uint32* Wh = Xl + 64 * XS;              // 32*72
    uint32* Wl = Wh + 32 * WWS;
    float*  Hcs = (float*)(Wl + 32 * WWS);  // [64][65]
    float*  Wbs = Hcs + 64 * 65;            // [64][10]
    float*  lg  = Wbs + 64 * 10;            // [64][12]
    int*    s_nei = (int*)(lg + 64 * 12);

    const int n    = blockIdx.y;
    const int b0   = blockIdx.x * 64;
    const int tid  = threadIdx.x;
    const int w    = tid >> 5;
    const int lane = tid & 31;
    const int g    = lane >> 2;
    const int tig  = lane & 3;
    const int rt   = w & 3;
    const int cb   = (w >> 2) * 32;         // 4 col tiles of 8

    if (tid < 8) s_nei[tid] = nei_of(n, tid);
    for (int idx = tid; idx < 640; idx += 256)
        lg[(idx / 10) * 12 + idx % 10] = bb[n * 10 + idx % 10];

    const float* Wan   = Wa + (size_t)n * 336 * 600 + (size_t)(STAGE2 ? 0 : 80) * 600;
    const float* ban   = ba + n * 600;
    const float* Wbn   = Wb + (size_t)n * 600 * 10;
    const float* featn = feat + (size_t)n * B * 256;

    constexpr int NKC = (KDIM + 31) / 32;

    for (int hc = 0; hc < 640; hc += 64) {
        float acc[4][4];
        #pragma unroll
        for (int j = 0; j < 4; j++) {
            int h0 = hc + cb + 8 * j + 2 * tig;
            float bv0 = (h0 < 600)     ? ban[h0]     : 0.f;
            float bv1 = (h0 + 1 < 600) ? ban[h0 + 1] : 0.f;
            acc[j][0] = bv0; acc[j][1] = bv1; acc[j][2] = bv0; acc[j][3] = bv1;
        }

        for (int kci = 0; kci < NKC; kci++) {
            const int kc = kci * 32;
            __syncthreads();
            // X fill: thread -> (b = tid/4, 8 consecutive k)
            {
                int bi = tid >> 2;
                int kk0 = (tid & 3) * 8;
                #pragma unroll
                for (int i = 0; i < 8; i++) {
                    int kk = kk0 + i;
                    int k = kc + kk;
                    float v = 0.f;
                    if (k < KDIM) {
                        if (STAGE2 && k < 80) {
                            int jn = k / 10, c = k - jn * 10;
                            int ne = s_nei[jn];
                            v = (ne >= 0) ? preds[((size_t)ne * B + b0 + bi) * 10 + c] : 0.f;
                        } else {
                            int ch = STAGE2 ? (k - 80) : k;
                            v = featn[((size_t)(b0 + bi)) * 256 + ch];
                        }
                    }
                    uint32 h, l;
                    split_tf(v, h, l);
                    Xh[bi * XS + kk] = h;
                    Xl[bi * XS + kk] = l;
                }
            }
            // W fill: thread -> (k row = tid/8, 8 consecutive h)
            {
                int kr = tid >> 3;
                int hh0 = (tid & 7) * 8;
                #pragma unroll
                for (int i = 0; i < 8; i++) {
                    int hh = hh0 + i;
                    int h = hc + hh;
                    float v = 0.f;
                    if (kc + kr < KDIM && h < 600)
                        v = Wan[(size_t)(kc + kr) * 600 + h];
                    uint32 hb, lb;
                    split_tf(v, hb, lb);
                    Wh[kr * WWS + hh] = hb;
                    Wl[kr * WWS + hh] = lb;
                }
            }
            __syncthreads();

            #pragma unroll
            for (int ksi = 0; ksi < 4; ksi++) {
                const int k0 = ksi * 8;
                const int ra = (16 * rt + g) * XS + k0 + tig;
                const int rb = (16 * rt + g + 8) * XS + k0 + tig;
                uint32 ah0 = Xh[ra],     ah1 = Xh[rb];
                uint32 ah2 = Xh[ra + 4], ah3 = Xh[rb + 4];
                uint32 al0 = Xl[ra],     al1 = Xl[rb];
                uint32 al2 = Xl[ra + 4], al3 = Xl[rb + 4];
                #pragma unroll
                for (int j = 0; j < 4; j++) {
                    const int col = cb + 8 * j + g;
                    uint32 bh0 = Wh[(k0 + tig) * WWS + col];
                    uint32 bh1 = Wh[(k0 + tig + 4) * WWS + col];
                    uint32 bl0 = Wl[(k0 + tig) * WWS + col];
                    uint32 bl1 = Wl[(k0 + tig + 4) * WWS + col];
                    mma_tf32(acc[j], al0, al1, al2, al3, bh0, bh1);
                    mma_tf32(acc[j], ah0, ah1, ah2, ah3, bl0, bl1);
                    mma_tf32(acc[j], ah0, ah1, ah2, ah3, bh0, bh1);
                }
            }
        }

        // tanh -> Hcs
        {
            int r0 = 16 * rt + g;
            #pragma unroll
            for (int j = 0; j < 4; j++) {
                int c0 = cb + 8 * j + 2 * tig;
                Hcs[r0 * 65 + c0]           = tanhf(acc[j][0]);
                Hcs[r0 * 65 + c0 + 1]       = tanhf(acc[j][1]);
                Hcs[(r0 + 8) * 65 + c0]     = tanhf(acc[j][2]);
                Hcs[(r0 + 8) * 65 + c0 + 1] = tanhf(acc[j][3]);
            }
        }
        for (int idx = tid; idx < 640; idx += 256) {
            int hi = idx / 10, c = idx % 10;
            int h = hc + hi;
            Wbs[hi * 10 + c] = (h < 600) ? Wbn[(size_t)h * 10 + c] : 0.f;
        }
        __syncthreads();

        if (tid < 128) {
            int bq = tid >> 1, c0 = (tid & 1) * 5;
            #pragma unroll
            for (int c = 0; c < 5; c++) {
                float s = 0.f;
                #pragma unroll 8
                for (int hj = 0; hj < 64; hj++)
                    s = fmaf(Hcs[bq * 65 + hj], Wbs[hj * 10 + c0 + c], s);
                lg[bq * 12 + c0 + c] += s;
            }
        }
        __syncthreads();
    }

    if (tid < 64) {
        float l[10];
        #pragma unroll
        for (int c = 0; c < 10; c++) l[c] = lg[tid * 12 + c];
        float m = l[0];
        #pragma unroll
        for (int c = 1; c < 10; c++) m = fmaxf(m, l[c]);
        float e[10]; float s = 0.f;
        #pragma unroll
        for (int c = 0; c < 10; c++) { e[c] = expf(l[c] - m); s += e[c]; }
        float inv = 1.f / s;
        size_t base = ((size_t)n * B + b0 + tid) * 10;
        #pragma unroll
        for (int c = 0; c < 10; c++) outp[base + c] = e[c] * inv;
    }
}

// ---------------------------------------------------------------------------
__global__ void mean_kernel(const float* __restrict__ second, float* __restrict__ outm, int B)
{
    int idx = blockIdx.x * blockDim.x + threadIdx.x;
    if (idx >= B * 10) return;
    float s = 0.f;
    #pragma unroll
    for (int n = 0; n < 25; n++) s += second[(size_t)n * B * 10 + idx];
    outm[idx] = s * (1.f / 25.f);
}

// ---------------------------------------------------------------------------
extern "C" void kernel_launch(void* const* d_in, const int* in_sizes, int n_in,
                              void* d_out, int out_size)
{
    const float* x  = (const float*)d_in[0];
    const float* W1 = (const float*)d_in[1];
    const float* b1 = (const float*)d_in[2];
    const float* g1 = (const float*)d_in[3];
    const float* be1= (const float*)d_in[4];
    const float* m1 = (const float*)d_in[5];
    const float* v1 = (const float*)d_in[6];
    const float* W2 = (const float*)d_in[7];
    const float* b2 = (const float*)d_in[8];
    const float* g2 = (const float*)d_in[9];
    const float* be2= (const float*)d_in[10];
    const float* m2 = (const float*)d_in[11];
    const float* v2 = (const float*)d_in[12];
    const float* W3 = (const float*)d_in[13];
    const float* b3 = (const float*)d_in[14];
    const float* g3 = (const float*)d_in[15];
    const float* be3= (const float*)d_in[16];
    const float* m3 = (const float*)d_in[17];
    const float* v3 = (const float*)d_in[18];
    const float* W4 = (const float*)d_in[19];
    const float* b4 = (const float*)d_in[20];
    const float* g4 = (const float*)d_in[21];
    const float* be4= (const float*)d_in[22];
    const float* m4 = (const float*)d_in[23];
    const float* v4 = (const float*)d_in[24];
    const float* Wa = (const float*)d_in[25];
    const float* ba = (const float*)d_in[26];
    const float* Wb = (const float*)d_in[27];
    const float* bb = (const float*)d_in[28];

    const int B = in_sizes[0] / (3 * 20 * 20);

    float *conv1b, *pool1b, *conv2b, *pool2b, *conv3b, *featb, *predsb, *scaleb, *biasb;
    float *wt2h, *wt2l, *wt3h, *wt3l, *wt4h, *wt4l;
    cudaGetSymbolAddress((void**)&conv1b, g_conv1);
    cudaGetSymbolAddress((void**)&pool1b, g_pool1);
    cudaGetSymbolAddress((void**)&conv2b, g_conv2);
    cudaGetSymbolAddress((void**)&pool2b, g_pool2);
    cudaGetSymbolAddress((void**)&conv3b, g_conv3);
    cudaGetSymbolAddress((void**)&featb,  g_feat);
    cudaGetSymbolAddress((void**)&predsb, g_preds);
    cudaGetSymbolAddress((void**)&scaleb, g_scale);
    cudaGetSymbolAddress((void**)&biasb,  g_bias);
    cudaGetSymbolAddress((void**)&wt2h, g_wt2h);
    cudaGetSymbolAddress((void**)&wt2l, g_wt2l);
    cudaGetSymbolAddress((void**)&wt3h, g_wt3h);
    cudaGetSymbolAddress((void**)&wt3l, g_wt3l);
    cudaGetSymbolAddress((void**)&wt4h, g_wt4h);
    cudaGetSymbolAddress((void**)&wt4l, g_wt4l);

    // smem sizes
    const int smem1   = (3 * 49 + 64 * 27) * 4;
    const int smemC34 = (2 * 64 * 52 + 2 * 48 * 136) * 4;   // 78848
    const int smemC2  = (2 * 128 * 52 + 2 * 48 * 72) * 4;   // 80896
    const int smemMLP = (2 * 64 * 36 + 2 * 32 * 72) * 4 + (64 * 65 + 64 * 10 + 64 * 12) * 4 + 32;

    cudaFuncSetAttribute(conv_bn_relu_kernel<3, 64, 3, 20, 64>,
                         cudaFuncAttributeMaxDynamicSharedMemorySize, smem1);
    cudaFuncSetAttribute(conv_mma_kernel<64, 128, 64, 10, 1, 128, false>,
                         cudaFuncAttributeMaxDynamicSharedMemorySize, smemC2);
    cudaFuncSetAttribute(conv_mma_kernel<128, 256, 128, 5, 2, 64, false>,
                         cudaFuncAttributeMaxDynamicSharedMemorySize, smemC34);
    cudaFuncSetAttribute(conv_mma_kernel<256, 256, 128, 5, 2, 64, true>,
                         cudaFuncAttributeMaxDynamicSharedMemorySize, smemC34);
    cudaFuncSetAttribute(mlp_kernel<256, false>,
                         cudaFuncAttributeMaxDynamicSharedMemorySize, smemMLP);
    cudaFuncSetAttribute(mlp_kernel<336, true>,
                         cudaFuncAttributeMaxDynamicSharedMemorySize, smemMLP);

    // BN fold
    bn_prep<<<1, 64>>> (b1, g1, be1, m1, v1, 64, 0);
    bn_prep<<<1, 128>>>(b2, g2, be2, m2, v2, 128, 64);
    bn_prep<<<1, 256>>>(b3, g3, be3, m3, v3, 256, 192);
    bn_prep<<<1, 256>>>(b4, g4, be4, m4, v4, 256, 448);

    // weight transpose + tf32 split
    wprep<<<(128 * 576 + 255) / 256, 256>>>(W2, wt2h, wt2l, 128, 576);
    wprep<<<(256 * 1152 + 255) / 256, 256>>>(W3, wt3h, wt3l, 256, 1152);
    wprep<<<(256 * 2304 + 255) / 256, 256>>>(W4, wt4h, wt4l, 256, 2304);

    // conv1 (scalar) -> pool1
    conv_bn_relu_kernel<3, 64, 3, 20, 64>
        <<<dim3(16, B), 64, smem1>>>(x, W1, scaleb + 0, biasb + 0, conv1b, B);
    {
        size_t total = (size_t)B * 64 * 100;
        maxpool_kernel<<<(unsigned)((total + 255) / 256), 256>>>(conv1b, pool1b, B, 64, 20);
    }
    // conv2 (tensor): [B,64,10,10] -> [B,128,10,10]
    conv_mma_kernel<64, 128, 64, 10, 1, 128, false>
        <<<dim3(B, 2), 256, smemC2>>>(pool1b, wt2h, wt2l, scaleb + 64, biasb + 64, conv2b, B);
    {
        size_t total = (size_t)B * 128 * 25;
        maxpool_kernel<<<(unsigned)((total + 255) / 256), 256>>>(conv2b, pool2b, B, 128, 10);
    }
    // conv3 (tensor): [B,128,5,5] -> [B,256,5,5]
    conv_mma_kernel<128, 256, 128, 5, 2, 64, false>
        <<<dim3(B / 2, 2), 256, smemC34>>>(pool2b, wt3h, wt3l, scaleb + 192, biasb + 192, conv3b, B);
    // conv4 (tensor): -> feats [25,B,256]
    conv_mma_kernel<256, 256, 128, 5, 2, 64, true>
        <<<dim3(B / 2, 2), 256, smemC34>>>(conv3b, wt4h, wt4l, scaleb + 448, biasb + 448, featb, B);

    float* out   = (float*)d_out;
    float* secnd = out + (size_t)B * 10;

    mlp_kernel<256, false><<<dim3(B / 64, 25), 256, smemMLP>>>(featb, predsb, Wa, ba, Wb, bb, predsb, B);
    mlp_kernel<336, true><<<dim3(B / 64, 25), 256, smemMLP>>>(featb, predsb, Wa, ba, Wb, bb, secnd, B);
    mean_kernel<<<(B * 10 + 255) / 256, 256>>>(secnd, out, B);
}

// round 10
// speedup vs baseline: 1.6839x; 1.6839x over previous
#include <cuda_runtime.h>
#include <cuda_bf16.h>
#include <math.h>
#include <stdint.h>

#define MAXB 8192
typedef unsigned int uint32;
typedef unsigned long long ull;

__device__ float  g_conv1 [(size_t)MAXB * 64 * 400];   // [B,64,20,20] float
__device__ uint32 g_pool1p[(size_t)MAXB * 64 * 100];   // [B,64,10,10] packed hi/lo bf16
__device__ float  g_conv2 [(size_t)MAXB * 128 * 100];  // [B,128,10,10] float
__device__ uint32 g_pool2p[(size_t)MAXB * 128 * 25];   // [B,128,5,5] packed
__device__ uint32 g_conv3p[(size_t)MAXB * 256 * 25];   // [B,256,5,5] packed
__device__ float  g_feat  [(size_t)25 * MAXB * 256];   // [25,B,256] float
__device__ float  g_preds [(size_t)25 * MAXB * 10];    // [25,B,10] float
__device__ float  g_scale[704];
__device__ float  g_bias[704];
// conv weights, pre-transposed [kpair][oc], bf16 pairs packed along k (hi & lo words)
__device__ uint32 g_wt2h[288 * 128],  g_wt2l[288 * 128];
__device__ uint32 g_wt3h[576 * 256],  g_wt3l[576 * 256];
__device__ uint32 g_wt4h[1152 * 256], g_wt4l[1152 * 256];

// ---------------------------------------------------------------------------
// helpers
// ---------------------------------------------------------------------------
__device__ __forceinline__ uint32 prmt(uint32 a, uint32 b, uint32 sel) {
    uint32 r; asm("prmt.b32 %0,%1,%2,%3;" : "=r"(r) : "r"(a), "r"(b), "r"(sel)); return r;
}
// pack one float as (bf16 hi)|(bf16 lo)<<16
__device__ __forceinline__ uint32 packval(float v) {
    unsigned short h = __bfloat16_as_ushort(__float2bfloat16(v));
    float hf = __bfloat162float(__ushort_as_bfloat16(h));
    unsigned short l = __bfloat16_as_ushort(__float2bfloat16(v - hf));
    return (uint32)h | ((uint32)l << 16);
}
// split two floats into (hi0,hi1) and (lo0,lo1) bf16x2 words
__device__ __forceinline__ void split2(float v0, float v1, uint32& hw, uint32& lw) {
    uint32 p0 = packval(v0), p1 = packval(v1);
    hw = prmt(p0, p1, 0x5410);   // hi0, hi1
    lw = prmt(p0, p1, 0x7632);   // lo0, lo1
}
__device__ __forceinline__ void mma_bf16(float* c, uint32 a0, uint32 a1, uint32 a2, uint32 a3,
                                         uint32 b0, uint32 b1) {
    asm volatile(
        "mma.sync.aligned.m16n8k16.row.col.f32.bf16.bf16.f32 "
        "{%0,%1,%2,%3},{%4,%5,%6,%7},{%8,%9},{%0,%1,%2,%3};"
        : "+f"(c[0]), "+f"(c[1]), "+f"(c[2]), "+f"(c[3])
        : "r"(a0), "r"(a1), "r"(a2), "r"(a3), "r"(b0), "r"(b1));
}
// FFMA2 (conv1 + MLP)
__device__ __forceinline__ ull pack2(float lo, float hi) {
    ull r; asm("mov.b64 %0, {%1, %2};" : "=l"(r) : "f"(lo), "f"(hi)); return r;
}
__device__ __forceinline__ void fma2(ull& d, ull a, ull b) {
    asm("fma.rn.f32x2 %0, %1, %2, %3;" : "=l"(d) : "l"(a), "l"(b), "l"(d));
}
__device__ __forceinline__ void unpack2(ull v, float& lo, float& hi) {
    asm("mov.b64 {%0, %1}, %2;" : "=f"(lo), "=f"(hi) : "l"(v));
}

// ---------------------------------------------------------------------------
__global__ void bn_prep(const float* __restrict__ b, const float* __restrict__ g,
                        const float* __restrict__ be, const float* __restrict__ m,
                        const float* __restrict__ v, int C, int off)
{
    int c = blockIdx.x * blockDim.x + threadIdx.x;
    if (c < C) {
        float sc = g[c] / sqrtf(v[c] + 1e-5f);
        g_scale[off + c] = sc;
        g_bias[off + c]  = (b[c] - m[c]) * sc + be[c];
    }
}

// conv weight prep: [oc][k] -> [kpair][oc], bf16 split, pairs packed along k
__global__ void wprep_bf(const float* __restrict__ w, uint32* __restrict__ wh,
                         uint32* __restrict__ wl, int OCT, int K)
{
    int idx = blockIdx.x * blockDim.x + threadIdx.x;
    int KP = K / 2;
    if (idx >= KP * OCT) return;
    int kp = idx / OCT, oc = idx - kp * OCT;
    float v0 = w[(size_t)oc * K + 2 * kp];
    float v1 = w[(size_t)oc * K + 2 * kp + 1];
    uint32 hw, lw;
    split2(v0, v1, hw, lw);
    wh[idx] = hw; wl[idx] = lw;
}

// ---------------------------------------------------------------------------
// conv1: scalar FFMA2 (3 input channels)
// ---------------------------------------------------------------------------
template<int IC, int OC, int ICCHUNK, int HW, int NTHREADS>
__launch_bounds__(NTHREADS, 2)
__global__ void conv_bn_relu_kernel(const float* __restrict__ in,
                                    const float* __restrict__ wt,
                                    const float* __restrict__ ks,
                                    const float* __restrict__ kb,
                                    float* __restrict__ out, int B)
{
    constexpr int TILES = HW / 5;
    constexpr int CH9 = ICCHUNK * 9;
    constexpr int WSTRIDE = (CH9 % 2 == 0) ? (CH9 + 1) : CH9;

    extern __shared__ float dyn[];
    float* in_s = dyn;
    float* w_s  = dyn + ICCHUNK * 49;

    const int tile = blockIdx.x;
    const int b    = blockIdx.y;
    const int ty0  = (tile / TILES) * 5;
    const int tx0  = (tile % TILES) * 5;
    const int oc   = threadIdx.x;

    ull   accp[5][2];
    float acc4[5];
    #pragma unroll
    for (int r = 0; r < 5; r++) { accp[r][0] = 0ull; accp[r][1] = 0ull; acc4[r] = 0.f; }

    for (int ic0 = 0; ic0 < IC; ic0 += ICCHUNK) {
        __syncthreads();
        for (int idx = threadIdx.x; idx < ICCHUNK * 49; idx += NTHREADS) {
            int i = idx / 49, r = idx % 49;
            int y = ty0 - 1 + r / 7;
            int x = tx0 - 1 + r % 7;
            float v = 0.f;
            if (y >= 0 && y < HW && x >= 0 && x < HW)
                v = in[(((size_t)b * IC + ic0 + i) * HW + y) * HW + x];
            in_s[idx] = v;
        }
        for (int idx = threadIdx.x; idx < OC * CH9; idx += NTHREADS) {
            int o = idx / CH9, r = idx % CH9;
            w_s[o * WSTRIDE + r] = wt[((size_t)o * IC + ic0) * 9 + r];
        }
        __syncthreads();

        #pragma unroll 1
        for (int i = 0; i < ICCHUNK; i++) {
            float ws[9]; ull wp2[9];
            const float* wq = &w_s[oc * WSTRIDE + i * 9];
            #pragma unroll
            for (int k = 0; k < 9; k++) { ws[k] = wq[k]; wp2[k] = pack2(ws[k], ws[k]); }
            #pragma unroll
            for (int r = 0; r < 7; r++) {
                float iv[7];
                #pragma unroll
                for (int c = 0; c < 7; c++) iv[c] = in_s[i * 49 + r * 7 + c];
                ull pr[5];
                #pragma unroll
                for (int s = 0; s < 5; s++) pr[s] = pack2(iv[s], iv[s + 1]);
                #pragma unroll
                for (int ky = 0; ky < 3; ky++) {
                    const int py = r - ky;
                    if (py >= 0 && py < 5) {
                        #pragma unroll
                        for (int kx = 0; kx < 3; kx++) {
                            fma2(accp[py][0], wp2[ky * 3 + kx], pr[kx]);
                            fma2(accp[py][1], wp2[ky * 3 + kx], pr[kx + 2]);
                            acc4[py] = fmaf(ws[ky * 3 + kx], iv[kx + 4], acc4[py]);
                        }
                    }
                }
            }
        }
    }

    float s  = ks[oc];
    float bs = kb[oc];
    #pragma unroll
    for (int py = 0; py < 5; py++) {
        float v0, v1, v2, v3;
        unpack2(accp[py][0], v0, v1);
        unpack2(accp[py][1], v2, v3);
        float row[5] = { v0, v1, v2, v3, acc4[py] };
        #pragma unroll
        for (int px = 0; px < 5; px++) {
            float y = fmaxf(fmaf(row[px], s, bs), 0.f);
            out[(((size_t)b * OC + oc) * HW + ty0 + py) * HW + tx0 + px] = y;
        }
    }
}

// ---------------------------------------------------------------------------
// Implicit-GEMM conv, bf16 split 3-MMA (m16n8k16).
// Input is PACKED (uint32 per pixel, hi|lo bf16). OUTMODE: 0 float planar,
// 1 packed planar, 2 float [node][b][oc].
// ---------------------------------------------------------------------------
template<int IC, int OCT, int OCB, int HW, int IMGS, int M, int OUTMODE>
__launch_bounds__(256)
__global__ void conv_mma_kernel(const uint32* __restrict__ in,
                                const uint32* __restrict__ wth,
                                const uint32* __restrict__ wtl,
                                const float* __restrict__ ks,
                                const float* __restrict__ kb,
                                void* __restrict__ outv, int B)
{
    constexpr int K   = IC * 9;
    constexpr int KP  = 24;             // k-pairs per chunk
    constexpr int HW2 = HW * HW;
    constexpr int MT  = M / 16;
    constexpr int AS  = 28;             // uint32 stride
    constexpr int WS  = OCB + 8;        // ≡ 8 mod 32

    extern __shared__ uint32 sm[];
    uint32* Ah = sm;
    uint32* Al = Ah + M * AS;
    uint32* Wh = Al + M * AS;
    uint32* Wl = Wh + KP * WS;

    const int b0   = blockIdx.x * IMGS;
    const int ocb0 = blockIdx.y * OCB;
    const int tid  = threadIdx.x;
    const int w    = tid >> 5;
    const int lane = tid & 31;
    const int g    = lane >> 2;
    const int tig  = lane & 3;
    const int rt    = (MT == 4) ? (w & 3) : w;
    const int cbase = (MT == 4) ? ((w >> 2) * 64) : 0;
    constexpr int NJ = 8;   // 8 col tiles of 8 => 64 cols per warp(-group)

    float acc[8][4];
    #pragma unroll
    for (int j = 0; j < 8; j++)
        #pragma unroll
        for (int q = 0; q < 4; q++) acc[j][q] = 0.f;

    for (int kc2 = 0; kc2 < K / 2; kc2 += KP) {
        __syncthreads();
        // A tile: packed pixels -> (hi,hi) / (lo,lo) pair words
        for (int idx = tid; idx < M * KP; idx += 256) {
            int row = idx / KP, kp = idx - row * KP;
            int k0 = (kc2 + kp) * 2;
            int img, p;
            if (IMGS == 2) { img = row >> 5; p = row & 31; }
            else           { img = 0;        p = row; }
            uint32 w0 = 0, w1 = 0;
            if (p < HW2) {
                int py = p / HW, px = p - py * HW;
                {
                    int c = k0 / 9, t = k0 - 9 * c;
                    int ky = t / 3, kx = t - 3 * ky;
                    int iy = py + ky - 1, ix = px + kx - 1;
                    if (iy >= 0 && iy < HW && ix >= 0 && ix < HW)
                        w0 = in[((size_t)(b0 + img) * IC + c) * HW2 + iy * HW + ix];
                }
                {
                    int k1 = k0 + 1;
                    int c = k1 / 9, t = k1 - 9 * c;
                    int ky = t / 3, kx = t - 3 * ky;
                    int iy = py + ky - 1, ix = px + kx - 1;
                    if (iy >= 0 && iy < HW && ix >= 0 && ix < HW)
                        w1 = in[((size_t)(b0 + img) * IC + c) * HW2 + iy * HW + ix];
                }
            }
            Ah[row * AS + kp] = prmt(w0, w1, 0x5410);
            Al[row * AS + kp] = prmt(w0, w1, 0x7632);
        }
        // weight tile (pre-split/packed in gmem)
        for (int idx = tid; idx < KP * OCB; idx += 256) {
            int kp = idx / OCB, oc = idx - kp * OCB;
            size_t gi = (size_t)(kc2 + kp) * OCT + ocb0 + oc;
            Wh[kp * WS + oc] = wth[gi];
            Wl[kp * WS + oc] = wtl[gi];
        }
        __syncthreads();

        #pragma unroll
        for (int ksi = 0; ksi < 3; ksi++) {
            const int kbp = ksi * 8;
            const int ra = (16 * rt + g) * AS + kbp + tig;
            const int rb = ra + 8 * AS;
            uint32 ah0 = Ah[ra],     ah1 = Ah[rb];
            uint32 ah2 = Ah[ra + 4], ah3 = Ah[rb + 4];
            uint32 al0 = Al[ra],     al1 = Al[rb];
            uint32 al2 = Al[ra + 4], al3 = Al[rb + 4];
            #pragma unroll
            for (int j = 0; j < NJ; j++) {
                const int col = cbase + 8 * j + g;
                uint32 bh0 = Wh[(kbp + tig) * WS + col];
                uint32 bh1 = Wh[(kbp + tig + 4) * WS + col];
                uint32 bl0 = Wl[(kbp + tig) * WS + col];
                uint32 bl1 = Wl[(kbp + tig + 4) * WS + col];
                mma_bf16(acc[j], al0, al1, al2, al3, bh0, bh1);
                mma_bf16(acc[j], ah0, ah1, ah2, ah3, bl0, bl1);
                mma_bf16(acc[j], ah0, ah1, ah2, ah3, bh0, bh1);
            }
        }
    }

    // epilogue
    const int r0 = 16 * rt + g;
    #pragma unroll
    for (int j = 0; j < NJ; j++) {
        int c0 = cbase + 8 * j + 2 * tig;
        int oc0 = ocb0 + c0;
        float s0 = ks[oc0],     bb0 = kb[oc0];
        float s1 = ks[oc0 + 1], bb1 = kb[oc0 + 1];
        float y00 = fmaxf(fmaf(acc[j][0], s0, bb0), 0.f);
        float y01 = fmaxf(fmaf(acc[j][1], s1, bb1), 0.f);
        float y10 = fmaxf(fmaf(acc[j][2], s0, bb0), 0.f);
        float y11 = fmaxf(fmaf(acc[j][3], s1, bb1), 0.f);
        #pragma unroll
        for (int half = 0; half < 2; half++) {
            int row = r0 + half * 8;
            float ya = half ? y10 : y00;
            float yb = half ? y11 : y01;
            int img, p;
            if (IMGS == 2) { img = row >> 5; p = row & 31; }
            else           { img = 0;        p = row; }
            if (p < HW2) {
                if (OUTMODE == 0) {
                    float* out = (float*)outv;
                    out[((size_t)(b0 + img) * OCT + oc0) * HW2 + p]     = ya;
                    out[((size_t)(b0 + img) * OCT + oc0 + 1) * HW2 + p] = yb;
                } else if (OUTMODE == 1) {
                    uint32* out = (uint32*)outv;
                    out[((size_t)(b0 + img) * OCT + oc0) * HW2 + p]     = packval(ya);
                    out[((size_t)(b0 + img) * OCT + oc0 + 1) * HW2 + p] = packval(yb);
                } else {
                    float* out = (float*)outv;
                    size_t base = ((size_t)p * B + b0 + img) * OCT + oc0;
                    out[base]     = ya;
                    out[base + 1] = yb;
                }
            }
        }
    }
}

// ---------------------------------------------------------------------------
// MaxPool2d(3,s=2,p=1), float in -> packed uint32 out
// ---------------------------------------------------------------------------
__global__ void maxpool_pack_kernel(const float* __restrict__ in, uint32* __restrict__ out,
                                    int B, int C, int H)
{
    int OH = H / 2;
    size_t total = (size_t)B * C * OH * OH;
    size_t idx = (size_t)blockIdx.x * blockDim.x + threadIdx.x;
    if (idx >= total) return;
    int ox = idx % OH;
    int oy = (idx / OH) % OH;
    size_t bc = idx / ((size_t)OH * OH);
    const float* p = in + bc * H * H;
    float m = -3.4e38f;
    #pragma unroll
    for (int dy = -1; dy <= 1; dy++) {
        int iy = 2 * oy + dy;
        if (iy < 0 || iy >= H) continue;
        #pragma unroll
        for (int dx = -1; dx <= 1; dx++) {
            int ix = 2 * ox + dx;
            if (ix < 0 || ix >= H) continue;
            m = fmaxf(m, p[iy * H + ix]);
        }
    }
    out[idx] = packval(m);
}

// ---------------------------------------------------------------------------
__device__ __forceinline__ int nei_of(int i, int j)
{
    int n[8]; int cnt = 0;
    if (i - 5 >= 0)                          n[cnt++] = i - 5;
    if (i % 5 != 0)                          n[cnt++] = i - 1;
    if ((i + 1) % 5 != 0)                    n[cnt++] = i + 1;
    if (i + 5 < 25)                          n[cnt++] = i + 5;
    if (i - 6 >= 0 && i % 5 != 0)            n[cnt++] = i - 6;
    if (i - 4 >= 0 && (i + 1) % 5 != 0)      n[cnt++] = i - 4;
    if (i + 4 < 25 && i % 5 != 0)            n[cnt++] = i + 4;
    if (i + 6 < 25 && (i + 1) % 5 != 0)      n[cnt++] = i + 6;
    while (cnt < 8) n[cnt++] = -1;
    return n[j];
}

// ---------------------------------------------------------------------------
// Fused per-node MLP, scalar FFMA2 (proven in R5)
// ---------------------------------------------------------------------------
template<int KDIM, bool STAGE2>
__launch_bounds__(256)
__global__ void mlp_kernel(const float* __restrict__ feat,   // [25][B][256]
                           const float* __restrict__ preds,  // [25][B][10]
                           const float* __restrict__ Wa,
                           const float* __restrict__ ba,
                           const float* __restrict__ Wb,
                           const float* __restrict__ bb,
                           float* __restrict__ outp,
                           int B)
{
    __shared__ __align__(16) float Xs[8][64];
    __shared__ __align__(16) float Was[8][64];
    __shared__ float Hcs[64][65];
    __shared__ float Wbs[64][10];
    __shared__ float lg[64][12];
    __shared__ int s_nei[8];

    const int n   = blockIdx.y;
    const int b0  = blockIdx.x * 64;
    const int tid = threadIdx.x;
    const int bgrp = tid & 15;
    const int hgrp = tid >> 4;

    if (tid < 8) s_nei[tid] = nei_of(n, tid);
    for (int idx = tid; idx < 640; idx += 256)
        lg[idx / 10][idx % 10] = bb[n * 10 + idx % 10];

    const float* Wan   = Wa + (size_t)n * 336 * 600 + (size_t)(STAGE2 ? 0 : 80) * 600;
    const float* ban   = ba + n * 600;
    const float* Wbn   = Wb + (size_t)n * 600 * 10;
    const float* featn = feat + (size_t)n * B * 256;

    for (int hc = 0; hc < 640; hc += 64) {
        ull accp[4][2];
        #pragma unroll
        for (int jp = 0; jp < 2; jp++) {
            int h0 = hc + hgrp * 4 + jp * 2;
            float bv0 = (h0     < 600) ? ban[h0]     : 0.f;
            float bv1 = (h0 + 1 < 600) ? ban[h0 + 1] : 0.f;
            ull bvp = pack2(bv0, bv1);
            #pragma unroll
            for (int i = 0; i < 4; i++) accp[i][jp] = bvp;
        }

        for (int k0 = 0; k0 < KDIM; k0 += 8) {
            __syncthreads();
            #pragma unroll
            for (int t = 0; t < 2; t++) {
                int e = tid * 2 + t;
                int bi = e >> 3, kj = e & 7;
                int k = k0 + kj;
                float v;
                if (STAGE2 && k < 80) {
                    int jn = k / 10, c = k - jn * 10;
                    int ne = s_nei[jn];
                    v = (ne >= 0) ? preds[((size_t)ne * B + b0 + bi) * 10 + c] : 0.f;
                } else {
                    int ch = STAGE2 ? (k - 80) : k;
                    v = featn[((size_t)(b0 + bi)) * 256 + ch];
                }
                Xs[kj][bi] = v;
            }
            #pragma unroll
            for (int t = 0; t < 2; t++) {
                int e = tid * 2 + t;
                int kj = e >> 6, hi = e & 63;
                int h = hc + hi;
                Was[kj][hi] = (h < 600) ? Wan[(size_t)(k0 + kj) * 600 + h] : 0.f;
            }
            __syncthreads();

            #pragma unroll
            for (int kj = 0; kj < 8; kj++) {
                float4 xv = *reinterpret_cast<const float4*>(&Xs[kj][bgrp * 4]);
                float4 wv = *reinterpret_cast<const float4*>(&Was[kj][hgrp * 4]);
                ull wh2[2] = { pack2(wv.x, wv.y), pack2(wv.z, wv.w) };
                ull xb2[4] = { pack2(xv.x, xv.x), pack2(xv.y, xv.y),
                               pack2(xv.z, xv.z), pack2(xv.w, xv.w) };
                #pragma unroll
                for (int i = 0; i < 4; i++) {
                    fma2(accp[i][0], xb2[i], wh2[0]);
                    fma2(accp[i][1], xb2[i], wh2[1]);
                }
            }
        }

        #pragma unroll
        for (int i = 0; i < 4; i++) {
            #pragma unroll
            for (int jp = 0; jp < 2; jp++) {
                float lo, hi;
                unpack2(accp[i][jp], lo, hi);
                Hcs[bgrp * 4 + i][hgrp * 4 + jp * 2]     = tanhf(lo);
                Hcs[bgrp * 4 + i][hgrp * 4 + jp * 2 + 1] = tanhf(hi);
            }
        }

        for (int idx = tid; idx < 640; idx += 256) {
            int hi = idx / 10, c = idx % 10;
            int h = hc + hi;
            Wbs[hi][c] = (h < 600) ? Wbn[(size_t)h * 10 + c] : 0.f;
        }
        __syncthreads();

        if (tid < 128) {
            int bq = tid >> 1, c0 = (tid & 1) * 5;
            #pragma unroll
            for (int c = 0; c < 5; c++) {
                float s = 0.f;
                #pragma unroll 8
                for (int hj = 0; hj < 64; hj++)
                    s = fmaf(Hcs[bq][hj], Wbs[hj][c0 + c], s);
                lg[bq][c0 + c] += s;
            }
        }
    }
    __syncthreads();

    if (tid < 64) {
        float l[10];
        #pragma unroll
        for (int c = 0; c < 10; c++) l[c] = lg[tid][c];
        float m = l[0];
        #pragma unroll
        for (int c = 1; c < 10; c++) m = fmaxf(m, l[c]);
        float e[10]; float s = 0.f;
        #pragma unroll
        for (int c = 0; c < 10; c++) { e[c] = expf(l[c] - m); s += e[c]; }
        float inv = 1.f / s;
        size_t base = ((size_t)n * B + b0 + tid) * 10;
        #pragma unroll
        for (int c = 0; c < 10; c++) outp[base + c] = e[c] * inv;
    }
}

// ---------------------------------------------------------------------------
__global__ void mean_kernel(const float* __restrict__ second, float* __restrict__ outm, int B)
{
    int idx = blockIdx.x * blockDim.x + threadIdx.x;
    if (idx >= B * 10) return;
    float s = 0.f;
    #pragma unroll
    for (int n = 0; n < 25; n++) s += second[(size_t)n * B * 10 + idx];
    outm[idx] = s * (1.f / 25.f);
}

// ---------------------------------------------------------------------------
extern "C" void kernel_launch(void* const* d_in, const int* in_sizes, int n_in,
                              void* d_out, int out_size)
{
    const float* x  = (const float*)d_in[0];
    const float* W1 = (const float*)d_in[1];
    const float* b1 = (const float*)d_in[2];
    const float* g1 = (const float*)d_in[3];
    const float* be1= (const float*)d_in[4];
    const float* m1 = (const float*)d_in[5];
    const float* v1 = (const float*)d_in[6];
    const float* W2 = (const float*)d_in[7];
    const float* b2 = (const float*)d_in[8];
    const float* g2 = (const float*)d_in[9];
    const float* be2= (const float*)d_in[10];
    const float* m2 = (const float*)d_in[11];
    const float* v2 = (const float*)d_in[12];
    const float* W3 = (const float*)d_in[13];
    const float* b3 = (const float*)d_in[14];
    const float* g3 = (const float*)d_in[15];
    const float* be3= (const float*)d_in[16];
    const float* m3 = (const float*)d_in[17];
    const float* v3 = (const float*)d_in[18];
    const float* W4 = (const float*)d_in[19];
    const float* b4 = (const float*)d_in[20];
    const float* g4 = (const float*)d_in[21];
    const float* be4= (const float*)d_in[22];
    const float* m4 = (const float*)d_in[23];
    const float* v4 = (const float*)d_in[24];
    const float* Wa = (const float*)d_in[25];
    const float* ba = (const float*)d_in[26];
    const float* Wb = (const float*)d_in[27];
    const float* bb = (const float*)d_in[28];

    const int B = in_sizes[0] / (3 * 20 * 20);

    float *conv1b, *conv2b, *featb, *predsb, *scaleb, *biasb;
    uint32 *pool1p, *pool2p, *conv3p;
    uint32 *wt2h, *wt2l, *wt3h, *wt3l, *wt4h, *wt4l;
    cudaGetSymbolAddress((void**)&conv1b, g_conv1);
    cudaGetSymbolAddress((void**)&pool1p, g_pool1p);
    cudaGetSymbolAddress((void**)&conv2b, g_conv2);
    cudaGetSymbolAddress((void**)&pool2p, g_pool2p);
    cudaGetSymbolAddress((void**)&conv3p, g_conv3p);
    cudaGetSymbolAddress((void**)&featb,  g_feat);
    cudaGetSymbolAddress((void**)&predsb, g_preds);
    cudaGetSymbolAddress((void**)&scaleb, g_scale);
    cudaGetSymbolAddress((void**)&biasb,  g_bias);
    cudaGetSymbolAddress((void**)&wt2h, g_wt2h);
    cudaGetSymbolAddress((void**)&wt2l, g_wt2l);
    cudaGetSymbolAddress((void**)&wt3h, g_wt3h);
    cudaGetSymbolAddress((void**)&wt3l, g_wt3l);
    cudaGetSymbolAddress((void**)&wt4h, g_wt4h);
    cudaGetSymbolAddress((void**)&wt4l, g_wt4l);

    const int smem1   = (3 * 49 + 64 * 27) * 4;
    const int smemC2  = (2 * 128 * 28 + 2 * 24 * 72) * 4;    // 42496
    const int smemC34 = (2 * 64 * 28 + 2 * 24 * 136) * 4;    // 40448

    cudaFuncSetAttribute(conv_bn_relu_kernel<3, 64, 3, 20, 64>,
                         cudaFuncAttributeMaxDynamicSharedMemorySize, smem1);
    cudaFuncSetAttribute(conv_mma_kernel<64, 128, 64, 10, 1, 128, 0>,
                         cudaFuncAttributeMaxDynamicSharedMemorySize, smemC2);
    cudaFuncSetAttribute(conv_mma_kernel<128, 256, 128, 5, 2, 64, 1>,
                         cudaFuncAttributeMaxDynamicSharedMemorySize, smemC34);
    cudaFuncSetAttribute(conv_mma_kernel<256, 256, 128, 5, 2, 64, 2>,
                         cudaFuncAttributeMaxDynamicSharedMemorySize, smemC34);

    // launch order chosen so launch #6 (ncu -s 5 -c 1) is conv2 (tensor kernel)
    bn_prep<<<1, 64>>> (b1, g1, be1, m1, v1, 64, 0);                       // 1
    conv_bn_relu_kernel<3, 64, 3, 20, 64>                                  // 2
        <<<dim3(16, B), 64, smem1>>>(x, W1, scaleb + 0, biasb + 0, conv1b, B);
    {
        size_t total = (size_t)B * 64 * 100;                               // 3
        maxpool_pack_kernel<<<(unsigned)((total + 255) / 256), 256>>>(conv1b, pool1p, B, 64, 20);
    }
    bn_prep<<<1, 128>>>(b2, g2, be2, m2, v2, 128, 64);                     // 4
    wprep_bf<<<(288 * 128 + 255) / 256, 256>>>(W2, wt2h, wt2l, 128, 576);  // 5
    conv_mma_kernel<64, 128, 64, 10, 1, 128, 0>                            // 6  <- profiled
        <<<dim3(B, 2), 256, smemC2>>>(pool1p, wt2h, wt2l, scaleb + 64, biasb + 64, conv2b, B);
    bn_prep<<<1, 256>>>(b3, g3, be3, m3, v3, 256, 192);
    bn_prep<<<1, 256>>>(b4, g4, be4, m4, v4, 256, 448);
    wprep_bf<<<(576 * 256 + 255) / 256, 256>>>(W3, wt3h, wt3l, 256, 1152);
    wprep_bf<<<(1152 * 256 + 255) / 256, 256>>>(W4, wt4h, wt4l, 256, 2304);
    {
        size_t total = (size_t)B * 128 * 25;
        maxpool_pack_kernel<<<(unsigned)((total + 255) / 256), 256>>>(conv2b, pool2p, B, 128, 10);
    }
    conv_mma_kernel<128, 256, 128, 5, 2, 64, 1>
        <<<dim3(B / 2, 2), 256, smemC34>>>(pool2p, wt3h, wt3l, scaleb + 192, biasb + 192, conv3p, B);
    conv_mma_kernel<256, 256, 128, 5, 2, 64, 2>
        <<<dim3(B / 2, 2), 256, smemC34>>>(conv3p, wt4h, wt4l, scaleb + 448, biasb + 448, featb, B);

    float* out   = (float*)d_out;
    float* secnd = out + (size_t)B * 10;

    mlp_kernel<256, false><<<dim3(B / 64, 25), 256>>>(featb, predsb, Wa, ba, Wb, bb, predsb, B);
    mlp_kernel<336, true><<<dim3(B / 64, 25), 256>>>(featb, predsb, Wa, ba, Wb, bb, secnd, B);
    mean_kernel<<<(B * 10 + 255) / 256, 256>>>(secnd, out, B);
}